// round 2
// baseline (speedup 1.0000x reference)
#include <cuda_runtime.h>
#include <cstdint>

#define BB 16
#define LL 256
#define DD 256
#define PP 20
#define AL 68     // padded smem leading dim (floats): conflict-free + 16B aligned
#define LT 64     // l-tile rows per block

// Scratch for inverse norms (no allocations allowed -> __device__ globals)
__device__ float g_inv1[BB*LL*PP];
__device__ float g_inv2[BB*LL*PP];

// ---------------------------------------------------------------------------
// Kernel 1: inv-norms.  grid = B*L rows, block = 640 threads (warp per p).
// inv[b,row,p] = rsqrt(max(sum_d (s[d]*k[p,d])^2, 1e-12))
// ---------------------------------------------------------------------------
__global__ void __launch_bounds__(640) norms_kernel(const float* __restrict__ s1,
                                                    const float* __restrict__ s2,
                                                    const float* __restrict__ ker) {
    __shared__ float r1[DD], r2[DD];
    int row = blockIdx.x;              // b*L + l
    int tid = threadIdx.x;
    if (tid < DD) {
        r1[tid] = s1[(size_t)row*DD + tid];
        r2[tid] = s2[(size_t)row*DD + tid];
    }
    __syncthreads();
    int p    = tid >> 5;               // 0..19
    int lane = tid & 31;
    const float* kp = ker + p*DD;
    float a1 = 0.f, a2 = 0.f;
    #pragma unroll
    for (int d = lane; d < DD; d += 32) {
        float k = kp[d];
        float w = k*k;
        a1 = fmaf(r1[d]*r1[d], w, a1);
        a2 = fmaf(r2[d]*r2[d], w, a2);
    }
    #pragma unroll
    for (int o = 16; o; o >>= 1) {
        a1 += __shfl_xor_sync(0xffffffffu, a1, o);
        a2 += __shfl_xor_sync(0xffffffffu, a2, o);
    }
    if (lane == 0) {
        g_inv1[row*PP + p] = rsqrtf(fmaxf(a1, 1e-12f));
        g_inv2[row*PP + p] = rsqrtf(fmaxf(a2, 1e-12f));
    }
}

// ---------------------------------------------------------------------------
// Kernel 2: per (b,p,l-tile) weighted GEMM + row-max.
// C[l,m] = sum_d (s1[l,d]*w[d]*inv1[l]) * s2[m,d];  out[l] = max_m C[l,m]*inv2[m]
// block: 256 threads, 16(tl) x 16(tm), each owns a 4x4 tile of a 64x64 C tile.
// ---------------------------------------------------------------------------
__global__ void __launch_bounds__(256) mpm_main(const float* __restrict__ s1,
                                                const float* __restrict__ s2,
                                                const float* __restrict__ ker,
                                                float* __restrict__ out) {
    extern __shared__ float sm[];
    float* sA     = sm;                  // DD*AL floats  (sA[d*AL + l])
    float* sB     = sm + DD*AL;          // DD*AL floats  (sB[d*AL + m])
    float* w_s    = sm + 2*DD*AL;        // DD floats
    float* inv1_s = w_s + DD;            // LT floats

    const int b  = blockIdx.z;
    const int p  = blockIdx.y;
    const int l0 = blockIdx.x * LT;
    const int tid = threadIdx.x;

    // preload per-perspective weights and inv1 for this l-tile
    {
        float k = ker[p*DD + tid];       // tid spans exactly 0..255 = D
        w_s[tid] = k*k;
    }
    if (tid < LT) inv1_s[tid] = g_inv1[((size_t)b*LL + l0 + tid)*PP + p];
    __syncthreads();

    // build sA (transposed, fully folded: s1 * w * inv1)
    const float* s1b = s1 + ((size_t)b*LL + l0)*DD;
    for (int idx = tid; idx < LT*DD; idx += 256) {
        int l = idx >> 8;                // D = 256
        int d = idx & (DD-1);
        sA[d*AL + l] = s1b[idx] * w_s[d] * inv1_s[l];
    }

    const int tl = tid & 15;             // l sub-tile
    const int tm = tid >> 4;             // m sub-tile
    const float NEG_INF = __int_as_float(0xff800000);
    float mx[4] = {NEG_INF, NEG_INF, NEG_INF, NEG_INF};

    const float* s2b = s2 + (size_t)b*LL*DD;

    for (int mt = 0; mt < 4; mt++) {
        __syncthreads();                 // previous sB reads done / sA built
        const float* s2t = s2b + (size_t)mt*LT*DD;
        for (int idx = tid; idx < LT*DD; idx += 256) {
            int m = idx >> 8;
            int d = idx & (DD-1);
            sB[d*AL + m] = s2t[idx];
        }
        __syncthreads();

        float c[4][4];
        #pragma unroll
        for (int i = 0; i < 4; i++)
            #pragma unroll
            for (int j = 0; j < 4; j++) c[i][j] = 0.f;

        const float* pa = sA + tl*4;
        const float* pb = sB + tm*4;
        #pragma unroll 4
        for (int d = 0; d < DD; d++) {
            float4 av = *(const float4*)(pa + d*AL);
            float4 bv = *(const float4*)(pb + d*AL);
            c[0][0] = fmaf(av.x, bv.x, c[0][0]);
            c[0][1] = fmaf(av.x, bv.y, c[0][1]);
            c[0][2] = fmaf(av.x, bv.z, c[0][2]);
            c[0][3] = fmaf(av.x, bv.w, c[0][3]);
            c[1][0] = fmaf(av.y, bv.x, c[1][0]);
            c[1][1] = fmaf(av.y, bv.y, c[1][1]);
            c[1][2] = fmaf(av.y, bv.z, c[1][2]);
            c[1][3] = fmaf(av.y, bv.w, c[1][3]);
            c[2][0] = fmaf(av.z, bv.x, c[2][0]);
            c[2][1] = fmaf(av.z, bv.y, c[2][1]);
            c[2][2] = fmaf(av.z, bv.z, c[2][2]);
            c[2][3] = fmaf(av.z, bv.w, c[2][3]);
            c[3][0] = fmaf(av.w, bv.x, c[3][0]);
            c[3][1] = fmaf(av.w, bv.y, c[3][1]);
            c[3][2] = fmaf(av.w, bv.z, c[3][2]);
            c[3][3] = fmaf(av.w, bv.w, c[3][3]);
        }

        // epilogue: scale by inv2[m] (>0, order-preserving) and fold into max
        const float* invp = g_inv2 + ((size_t)b*LL + mt*LT + tm*4)*PP + p;
        #pragma unroll
        for (int j = 0; j < 4; j++) {
            float iv = invp[j*PP];
            mx[0] = fmaxf(mx[0], c[0][j]*iv);
            mx[1] = fmaxf(mx[1], c[1][j]*iv);
            mx[2] = fmaxf(mx[2], c[2][j]*iv);
            mx[3] = fmaxf(mx[3], c[3][j]*iv);
        }
    }

    __syncthreads();                     // sB reads done -> reuse as reduction buf
    float* red = sB;                     // [16 tm][64 l]
    #pragma unroll
    for (int i = 0; i < 4; i++) red[tm*LT + tl*4 + i] = mx[i];
    __syncthreads();

    if (tid < LT) {
        float m = red[tid];
        #pragma unroll
        for (int t = 1; t < 16; t++) m = fmaxf(m, red[t*LT + tid]);
        out[((size_t)b*LL + l0 + tid)*PP + p] = m;
    }
}

// ---------------------------------------------------------------------------
extern "C" void kernel_launch(void* const* d_in, const int* in_sizes, int n_in,
                              void* d_out, int out_size) {
    const float* s1  = (const float*)d_in[0];
    const float* s2  = (const float*)d_in[1];
    const float* ker = (const float*)d_in[2];
    float* out = (float*)d_out;

    size_t smem = (size_t)(2*DD*AL + DD + LT) * sizeof(float);   // ~140.5 KB
    cudaFuncSetAttribute(mpm_main, cudaFuncAttributeMaxDynamicSharedMemorySize,
                         (int)smem);

    norms_kernel<<<BB*LL, 640>>>(s1, s2, ker);
    dim3 grid(LL/LT, PP, BB);
    mpm_main<<<grid, 256, smem>>>(s1, s2, ker, out);
}

// round 4
// speedup vs baseline: 3.4213x; 3.4213x over previous
#include <cuda_runtime.h>
#include <cuda_bf16.h>
#include <cstdint>

#define BB 16
#define LL 256
#define DD 256
#define PP 20
#define APAD 264            // padded K stride (elements) for ldmatrix, 16B-aligned rows

// Scratch for inverse norms (no allocations allowed -> __device__ globals)
__device__ float g_inv1[BB*LL*PP];
__device__ float g_inv2[BB*LL*PP];

// ---------------------------------------------------------------------------
// Kernel 1: inv-norms.  grid = B*L rows, block = 640 threads (warp per p).
// inv[b,row,p] = rsqrt(max(sum_d (s[d]*k[p,d])^2, 1e-12))
// ---------------------------------------------------------------------------
__global__ void __launch_bounds__(640) norms_kernel(const float* __restrict__ s1,
                                                    const float* __restrict__ s2,
                                                    const float* __restrict__ ker) {
    __shared__ float r1[DD], r2[DD];
    int row = blockIdx.x;
    int tid = threadIdx.x;
    if (tid < DD) {
        r1[tid] = s1[(size_t)row*DD + tid];
        r2[tid] = s2[(size_t)row*DD + tid];
    }
    __syncthreads();
    int p    = tid >> 5;
    int lane = tid & 31;
    const float* kp = ker + p*DD;
    float a1 = 0.f, a2 = 0.f;
    #pragma unroll
    for (int d = lane; d < DD; d += 32) {
        float k = kp[d];
        float w = k*k;
        a1 = fmaf(r1[d]*r1[d], w, a1);
        a2 = fmaf(r2[d]*r2[d], w, a2);
    }
    #pragma unroll
    for (int o = 16; o; o >>= 1) {
        a1 += __shfl_xor_sync(0xffffffffu, a1, o);
        a2 += __shfl_xor_sync(0xffffffffu, a2, o);
    }
    if (lane == 0) {
        g_inv1[row*PP + p] = rsqrtf(fmaxf(a1, 1e-12f));
        g_inv2[row*PP + p] = rsqrtf(fmaxf(a2, 1e-12f));
    }
}

// ---------------------------------------------------------------------------
// mma.sync / ldmatrix helpers (baseline PTX — compiles for compute_103)
// ---------------------------------------------------------------------------
__device__ __forceinline__ uint32_t smem_u32(const void* p) {
    uint32_t a;
    asm("{ .reg .u64 t; cvta.to.shared.u64 t, %1; cvt.u32.u64 %0, t; }" : "=r"(a) : "l"(p));
    return a;
}

#define LDSM4(r, addr) \
    asm volatile("ldmatrix.sync.aligned.m8n8.x4.shared.b16 {%0,%1,%2,%3}, [%4];" \
                 : "=r"((r)[0]), "=r"((r)[1]), "=r"((r)[2]), "=r"((r)[3]) : "r"(addr))

#define MMA16816(c, a, b0, b1) \
    asm volatile("mma.sync.aligned.m16n8k16.row.col.f32.bf16.bf16.f32 " \
                 "{%0,%1,%2,%3}, {%4,%5,%6,%7}, {%8,%9}, {%0,%1,%2,%3};" \
                 : "+f"((c)[0]), "+f"((c)[1]), "+f"((c)[2]), "+f"((c)[3]) \
                 : "r"((a)[0]), "r"((a)[1]), "r"((a)[2]), "r"((a)[3]), "r"(b0), "r"(b1))

// ---------------------------------------------------------------------------
// smem layout (bytes)
// ---------------------------------------------------------------------------
#define SZ_A   (128*APAD*2)        // 67584
#define SZ_B   (64*APAD*2)         // 33792
#define OFF_AHI 0
#define OFF_ALO (SZ_A)
#define OFF_BHI (2*SZ_A)
#define OFF_BLO (2*SZ_A + SZ_B)
#define OFF_W   (2*SZ_A + 2*SZ_B)           // 256 f32
#define OFF_RED (OFF_W + 1024)              // 4*128 f32
#define SMEM_SZ (OFF_RED + 2048)            // 205824 B

__device__ __forceinline__ uint32_t pk2(float x, float y) {
    __nv_bfloat162 t = __floats2bfloat162_rn(x, y);
    return reinterpret_cast<uint32_t&>(t);
}
__device__ __forceinline__ void split8(const float* a, uint4& hv, uint4& lv) {
    float h[8], lo[8];
    #pragma unroll
    for (int i = 0; i < 8; i++) {
        h[i]  = __bfloat162float(__float2bfloat16_rn(a[i]));
        lo[i] = a[i] - h[i];
    }
    hv = make_uint4(pk2(h[0],h[1]),  pk2(h[2],h[3]),  pk2(h[4],h[5]),  pk2(h[6],h[7]));
    lv = make_uint4(pk2(lo[0],lo[1]),pk2(lo[2],lo[3]),pk2(lo[4],lo[5]),pk2(lo[6],lo[7]));
}

// ---------------------------------------------------------------------------
// Kernel 2: per (b, p, l-half) 128x256x256 weighted GEMM on HMMA (bf16 x3
// split, fp32 accum) with fused row-max.
// 8 warps: wl = wid&1 (64-row l half), wm = wid>>1 (16-col m group).
// ---------------------------------------------------------------------------
__global__ void __launch_bounds__(256, 1) mpm_mma(const float* __restrict__ s1,
                                                  const float* __restrict__ s2,
                                                  const float* __restrict__ ker,
                                                  float* __restrict__ out) {
    extern __shared__ char smem[];
    const uint32_t sbase = smem_u32(smem);
    float* w_s = (float*)(smem + OFF_W);
    float* red = (float*)(smem + OFF_RED);

    const int b   = blockIdx.z;
    const int p   = blockIdx.y;
    const int l0  = blockIdx.x * 128;
    const int tid = threadIdx.x;
    const int wid = tid >> 5;
    const int lane = tid & 31;
    const int wl = wid & 1;
    const int wm = wid >> 1;

    // per-perspective weights w = k^2
    {
        float k = ker[p*DD + tid];          // tid spans 0..255 = D
        w_s[tid] = k*k;
    }
    __syncthreads();

    // ---- Build A (once): 128 l-rows x 256 d, folded s1*w*inv1, hi/lo bf16 ----
    {
        const float4* s1b = (const float4*)(s1 + ((size_t)b*LL + l0)*DD);
        const float* invp = g_inv1 + ((size_t)b*LL + l0)*PP + p;
        for (int g = tid; g < 128*32; g += 256) {
            int row = g >> 5, grp = g & 31, d0 = grp * 8;
            float4 f0 = s1b[row*64 + grp*2];
            float4 f1 = s1b[row*64 + grp*2 + 1];
            float4 w0 = *(const float4*)(w_s + d0);
            float4 w1 = *(const float4*)(w_s + d0 + 4);
            float iv = __ldg(invp + row*PP);
            float a[8] = { f0.x*w0.x*iv, f0.y*w0.y*iv, f0.z*w0.z*iv, f0.w*w0.w*iv,
                           f1.x*w1.x*iv, f1.y*w1.y*iv, f1.z*w1.z*iv, f1.w*w1.w*iv };
            uint4 hv, lv; split8(a, hv, lv);
            uint32_t so = (uint32_t)(row*APAD + d0) * 2;
            *(uint4*)(smem + OFF_AHI + so) = hv;
            *(uint4*)(smem + OFF_ALO + so) = lv;
        }
    }

    // per-thread ldmatrix base addresses
    // A: tile t of x4: row = (t&1)*8 + (lane&7), kofs = (t>>1)*8
    const uint32_t a_off = (uint32_t)(((wl*64 + ((lane>>3)&1)*8 + (lane&7))*APAD
                                       + (lane>>4)*8) * 2);
    const uint32_t aH = sbase + OFF_AHI + a_off;
    const uint32_t aL = sbase + OFF_ALO + a_off;
    // B: tile t of x4: n = (t>>1)*8 + (lane&7), kofs = (t&1)*8
    const uint32_t b_off = (uint32_t)(((wm*16 + ((lane>>3)>>1)*8 + (lane&7))*APAD
                                       + ((lane>>3)&1)*8) * 2);
    const uint32_t bH = sbase + OFF_BHI + b_off;
    const uint32_t bL = sbase + OFF_BLO + b_off;

    const float NEG_INF = __int_as_float(0xff800000);
    float mx[4][2];
    #pragma unroll
    for (int i = 0; i < 4; i++) { mx[i][0] = NEG_INF; mx[i][1] = NEG_INF; }

    for (int mt = 0; mt < 4; mt++) {
        __syncthreads();   // A ready (iter 0) / previous B reads complete

        // ---- Build B chunk: 64 m-rows, folded s2*inv2, hi/lo bf16 ----
        {
            const float4* s2b = (const float4*)(s2 + ((size_t)b*LL + mt*64)*DD);
            const float* invp = g_inv2 + ((size_t)b*LL + mt*64)*PP + p;
            for (int g = tid; g < 64*32; g += 256) {
                int row = g >> 5, grp = g & 31, d0 = grp * 8;
                float4 f0 = s2b[row*64 + grp*2];
                float4 f1 = s2b[row*64 + grp*2 + 1];
                float iv = __ldg(invp + row*PP);
                float a[8] = { f0.x*iv, f0.y*iv, f0.z*iv, f0.w*iv,
                               f1.x*iv, f1.y*iv, f1.z*iv, f1.w*iv };
                uint4 hv, lv; split8(a, hv, lv);
                uint32_t so = (uint32_t)(row*APAD + d0) * 2;
                *(uint4*)(smem + OFF_BHI + so) = hv;
                *(uint4*)(smem + OFF_BLO + so) = lv;
            }
        }
        __syncthreads();

        float c[4][2][4];
        #pragma unroll
        for (int i = 0; i < 4; i++)
            #pragma unroll
            for (int j = 0; j < 2; j++)
                #pragma unroll
                for (int q = 0; q < 4; q++) c[i][j][q] = 0.f;

        #pragma unroll 4
        for (int ks = 0; ks < 16; ks++) {
            const uint32_t ko = ks * 32;           // 16 bf16 = 32 bytes
            uint32_t ah[4][4], al[4][4], bh[4], bl[4];
            #pragma unroll
            for (int i = 0; i < 4; i++) {
                LDSM4(ah[i], aH + i*(16*APAD*2) + ko);
                LDSM4(al[i], aL + i*(16*APAD*2) + ko);
            }
            LDSM4(bh, bH + ko);
            LDSM4(bl, bL + ko);
            #pragma unroll
            for (int i = 0; i < 4; i++) {
                #pragma unroll
                for (int j = 0; j < 2; j++) {
                    MMA16816(c[i][j], ah[i], bh[2*j], bh[2*j+1]);
                    MMA16816(c[i][j], al[i], bh[2*j], bh[2*j+1]);
                    MMA16816(c[i][j], ah[i], bl[2*j], bl[2*j+1]);
                }
            }
        }

        // fold this m-chunk into running row max
        #pragma unroll
        for (int i = 0; i < 4; i++) {
            float v0 = NEG_INF, v1 = NEG_INF;
            #pragma unroll
            for (int j = 0; j < 2; j++) {
                v0 = fmaxf(v0, fmaxf(c[i][j][0], c[i][j][1]));   // row r
                v1 = fmaxf(v1, fmaxf(c[i][j][2], c[i][j][3]));   // row r+8
            }
            mx[i][0] = fmaxf(mx[i][0], v0);
            mx[i][1] = fmaxf(mx[i][1], v1);
        }
    }

    // reduce across the 4 threads sharing each row (lane&3 = column groups)
    #pragma unroll
    for (int i = 0; i < 4; i++)
        #pragma unroll
        for (int h = 0; h < 2; h++) {
            float v = mx[i][h];
            v = fmaxf(v, __shfl_xor_sync(0xffffffffu, v, 1));
            v = fmaxf(v, __shfl_xor_sync(0xffffffffu, v, 2));
            mx[i][h] = v;
        }

    __syncthreads();        // B reads done; red region free
    if ((lane & 3) == 0) {
        int r = lane >> 2;
        #pragma unroll
        for (int i = 0; i < 4; i++) {
            red[wm*128 + wl*64 + i*16 + r]     = mx[i][0];
            red[wm*128 + wl*64 + i*16 + 8 + r] = mx[i][1];
        }
    }
    __syncthreads();

    if (tid < 128) {
        float m = red[tid];
        m = fmaxf(m, red[128 + tid]);
        m = fmaxf(m, red[256 + tid]);
        m = fmaxf(m, red[384 + tid]);
        out[((size_t)b*LL + l0 + tid)*PP + p] = m;
    }
}

// ---------------------------------------------------------------------------
extern "C" void kernel_launch(void* const* d_in, const int* in_sizes, int n_in,
                              void* d_out, int out_size) {
    const float* s1  = (const float*)d_in[0];
    const float* s2  = (const float*)d_in[1];
    const float* ker = (const float*)d_in[2];
    float* out = (float*)d_out;

    cudaFuncSetAttribute(mpm_mma, cudaFuncAttributeMaxDynamicSharedMemorySize, SMEM_SZ);

    norms_kernel<<<BB*LL, 640>>>(s1, s2, ker);
    dim3 grid(2, PP, BB);
    mpm_mma<<<grid, 256, SMEM_SZ>>>(s1, s2, ker, out);
}

// round 5
// speedup vs baseline: 3.4769x; 1.0163x over previous
#include <cuda_runtime.h>
#include <cuda_bf16.h>
#include <cstdint>

#define BB 16
#define LL 256
#define DD 256
#define PP 20

// Device-global scratch (no allocations allowed)
__device__ float g_inv1[BB*LL*PP];
__device__ float g_inv2[BB*LL*PP];
__device__ uint4 g_s2h[BB*LL*DD/8];   // bf16 hi split of s2, row-major
__device__ uint4 g_s2l[BB*LL*DD/8];   // bf16 lo split of s2

// ---------------------------------------------------------------------------
// helpers
// ---------------------------------------------------------------------------
__device__ __forceinline__ uint32_t smem_u32(const void* p) {
    uint32_t a;
    asm("{ .reg .u64 t; cvta.to.shared.u64 t, %1; cvt.u32.u64 %0, t; }" : "=r"(a) : "l"(p));
    return a;
}
__device__ __forceinline__ uint32_t pk2(float x, float y) {
    __nv_bfloat162 t = __floats2bfloat162_rn(x, y);
    return reinterpret_cast<uint32_t&>(t);
}
__device__ __forceinline__ void split8(const float* a, uint4& hv, uint4& lv) {
    float h[8], lo[8];
    #pragma unroll
    for (int i = 0; i < 8; i++) {
        h[i]  = __bfloat162float(__float2bfloat16_rn(a[i]));
        lo[i] = a[i] - h[i];
    }
    hv = make_uint4(pk2(h[0],h[1]),  pk2(h[2],h[3]),  pk2(h[4],h[5]),  pk2(h[6],h[7]));
    lv = make_uint4(pk2(lo[0],lo[1]),pk2(lo[2],lo[3]),pk2(lo[4],lo[5]),pk2(lo[6],lo[7]));
}

#define LDSM4(r, addr) \
    asm volatile("ldmatrix.sync.aligned.m8n8.x4.shared.b16 {%0,%1,%2,%3}, [%4];" \
                 : "=r"((r)[0]), "=r"((r)[1]), "=r"((r)[2]), "=r"((r)[3]) : "r"(addr))
#define LDSM2(r, addr) \
    asm volatile("ldmatrix.sync.aligned.m8n8.x2.shared.b16 {%0,%1}, [%2];" \
                 : "=r"((r)[0]), "=r"((r)[1]) : "r"(addr))
#define MMA16816(c, a, b0, b1) \
    asm volatile("mma.sync.aligned.m16n8k16.row.col.f32.bf16.bf16.f32 " \
                 "{%0,%1,%2,%3}, {%4,%5,%6,%7}, {%8,%9}, {%0,%1,%2,%3};" \
                 : "+f"((c)[0]), "+f"((c)[1]), "+f"((c)[2]), "+f"((c)[3]) \
                 : "r"((a)[0]), "r"((a)[1]), "r"((a)[2]), "r"((a)[3]), "r"(b0), "r"(b1))
#define CP16(dst, src) \
    asm volatile("cp.async.cg.shared.global [%0], [%1], 16;" :: "r"(dst), "l"(src))
#define CPCOMMIT() asm volatile("cp.async.commit_group;" ::: "memory")
#define CPWAIT1()  asm volatile("cp.async.wait_group 1;" ::: "memory")
#define CPWAIT0()  asm volatile("cp.async.wait_group 0;" ::: "memory")

// ---------------------------------------------------------------------------
// Kernel 1: inv-norms.  grid = B*L rows, block = 640 threads (warp per p).
// ---------------------------------------------------------------------------
__global__ void __launch_bounds__(640) norms_kernel(const float* __restrict__ s1,
                                                    const float* __restrict__ s2,
                                                    const float* __restrict__ ker) {
    __shared__ float r1[DD], r2[DD];
    int row = blockIdx.x;
    int tid = threadIdx.x;
    if (tid < DD) {
        r1[tid] = s1[(size_t)row*DD + tid];
        r2[tid] = s2[(size_t)row*DD + tid];
    }
    __syncthreads();
    int p    = tid >> 5;
    int lane = tid & 31;
    const float* kp = ker + p*DD;
    float a1 = 0.f, a2 = 0.f;
    #pragma unroll
    for (int d = lane; d < DD; d += 32) {
        float k = kp[d];
        float w = k*k;
        a1 = fmaf(r1[d]*r1[d], w, a1);
        a2 = fmaf(r2[d]*r2[d], w, a2);
    }
    #pragma unroll
    for (int o = 16; o; o >>= 1) {
        a1 += __shfl_xor_sync(0xffffffffu, a1, o);
        a2 += __shfl_xor_sync(0xffffffffu, a2, o);
    }
    if (lane == 0) {
        g_inv1[row*PP + p] = rsqrtf(fmaxf(a1, 1e-12f));
        g_inv2[row*PP + p] = rsqrtf(fmaxf(a2, 1e-12f));
    }
}

// ---------------------------------------------------------------------------
// Kernel 1b: split s2 into bf16 hi/lo in GMEM (p-independent B operand)
// ---------------------------------------------------------------------------
__global__ void __launch_bounds__(256) split_kernel(const float* __restrict__ s2) {
    int i = blockIdx.x*256 + threadIdx.x;        // uint4 index (8 floats)
    const float4* src = (const float4*)s2 + (size_t)i*2;
    float4 f0 = src[0], f1 = src[1];
    float a[8] = { f0.x, f0.y, f0.z, f0.w, f1.x, f1.y, f1.z, f1.w };
    uint4 hv, lv; split8(a, hv, lv);
    g_s2h[i] = hv;
    g_s2l[i] = lv;
}

// ---------------------------------------------------------------------------
// smem layout (bytes). A: 128 rows x 512B (swizzled). B: 2 stages x (hi+lo).
// ---------------------------------------------------------------------------
#define OFF_AHI  0                 // 65536
#define OFF_ALO  65536             // 65536
#define OFF_B    131072            // stage s: hi @ +s*32768, lo @ +s*32768+16384
#define OFF_W    196608            // 256 f32
#define OFF_INV1 197632            // 128 f32
#define OFF_INV2 198144            // 256 f32
#define OFF_RED  199168            // 512 f32
#define SMEM_SZ  201216

// swizzled offset within a 512B-row tile: seg = 16B column index (0..31)
__device__ __forceinline__ uint32_t swz(int row, int seg) {
    return (uint32_t)(row*512 + ((seg ^ (row & 7)) << 4));
}

// ---------------------------------------------------------------------------
// Kernel 2: per (b, p, l-half) 128x256x256 weighted GEMM on HMMA bf16x3,
// fp32 accum, cp.async-streamed B, fused row-max.
// warps: wl = wid&1 (64-row l half), wm = wid>>1 (8-col n group per chunk).
// ---------------------------------------------------------------------------
__global__ void __launch_bounds__(256, 1) mpm_mma(const float* __restrict__ s1,
                                                  const float* __restrict__ ker,
                                                  float* __restrict__ out) {
    extern __shared__ char smem[];
    const uint32_t sbase = smem_u32(smem);
    float* w_s    = (float*)(smem + OFF_W);
    float* inv1_s = (float*)(smem + OFF_INV1);
    float* inv2_s = (float*)(smem + OFF_INV2);
    float* red    = (float*)(smem + OFF_RED);

    const int b   = blockIdx.z;
    const int p   = blockIdx.y;
    const int l0  = blockIdx.x * 128;
    const int tid = threadIdx.x;
    const int wid = tid >> 5;
    const int lane = tid & 31;
    const int wl = wid & 1;
    const int wm = wid >> 1;

    // ---- prefetch B chunk 0 (32 m-rows x 256 d, hi+lo) via cp.async ----
    const char* s2h_b = (const char*)g_s2h + (size_t)b*LL*DD*2;
    const char* s2l_b = (const char*)g_s2l + (size_t)b*LL*DD*2;
    {
        const uint32_t dstb = sbase + OFF_B;           // stage 0
        #pragma unroll
        for (int j = 0; j < 4; j++) {
            int s = tid + j*256;                        // 16B segment 0..1023
            int row = s >> 5, c = s & 31;
            uint32_t so = swz(row, c);
            CP16(dstb + so,         s2h_b + s*16);
            CP16(dstb + 16384 + so, s2l_b + s*16);
        }
    }
    CPCOMMIT();

    // ---- per-p weights + inverse norms into smem ----
    {
        float k = ker[p*DD + tid];                      // tid spans 0..255 = D
        w_s[tid] = k*k;
        inv2_s[tid] = g_inv2[((size_t)b*LL + tid)*PP + p];
    }
    if (tid < 128) inv1_s[tid] = g_inv1[((size_t)b*LL + l0 + tid)*PP + p];
    __syncthreads();

    // ---- build A once: 128 l-rows x 256 d, a = s1 * k^2, hi/lo bf16 ----
    {
        const float4* s1b = (const float4*)(s1 + ((size_t)b*LL + l0)*DD);
        #pragma unroll 4
        for (int g = tid; g < 128*32; g += 256) {
            int row = g >> 5, grp = g & 31, d0 = grp * 8;
            float4 f0 = s1b[row*64 + grp*2];
            float4 f1 = s1b[row*64 + grp*2 + 1];
            float4 w0 = *(const float4*)(w_s + d0);
            float4 w1 = *(const float4*)(w_s + d0 + 4);
            float a[8] = { f0.x*w0.x, f0.y*w0.y, f0.z*w0.z, f0.w*w0.w,
                           f1.x*w1.x, f1.y*w1.y, f1.z*w1.z, f1.w*w1.w };
            uint4 hv, lv; split8(a, hv, lv);
            uint32_t so = swz(row, grp);
            *(uint4*)(smem + OFF_AHI + so) = hv;
            *(uint4*)(smem + OFF_ALO + so) = lv;
        }
    }

    // ---- per-thread ldmatrix bases ----
    // A x4 tiles: row = wl*64 + i*16 + ((lane>>3)&1)*8 + (lane&7), k-half = lane>>4
    const int a_row0 = wl*64 + ((lane>>3)&1)*8 + (lane&7);
    const uint32_t a_rb = sbase + OFF_AHI + (uint32_t)a_row0*512;
    const int thi = lane >> 4;
    const int rx  = lane & 7;
    // B x2 tiles: n = wm*8 + (lane&7), k-half = (lane>>3)&1
    const int b_row = wm*8 + (lane & 7);
    const int tb = (lane >> 3) & 1;
    const uint32_t b_rowoff = (uint32_t)b_row*512;

    const float NEG_INF = __int_as_float(0xff800000);
    float mx[4][2];
    #pragma unroll
    for (int i = 0; i < 4; i++) { mx[i][0] = NEG_INF; mx[i][1] = NEG_INF; }

    for (int mt = 0; mt < 8; mt++) {
        // prefetch next chunk into alternate stage, then wait for current
        if (mt < 7) {
            const uint32_t dstb = sbase + OFF_B + ((mt+1)&1)*32768;
            const size_t srcoff = (size_t)(mt+1)*32*512;   // 32 rows x 512B
            #pragma unroll
            for (int j = 0; j < 4; j++) {
                int s = tid + j*256;
                int row = s >> 5, c = s & 31;
                uint32_t so = swz(row, c);
                CP16(dstb + so,         s2h_b + srcoff + s*16);
                CP16(dstb + 16384 + so, s2l_b + srcoff + s*16);
            }
            CPCOMMIT();
            CPWAIT1();
        } else {
            CPWAIT0();
        }
        __syncthreads();     // chunk mt visible (and A on first iter)

        const uint32_t bhB = sbase + OFF_B + (mt&1)*32768 + b_rowoff;
        const uint32_t blB = bhB + 16384;

        float c[4][4];
        #pragma unroll
        for (int i = 0; i < 4; i++)
            #pragma unroll
            for (int q = 0; q < 4; q++) c[i][q] = 0.f;

        #pragma unroll 8
        for (int ks = 0; ks < 16; ks++) {
            uint32_t bofs = (uint32_t)(((ks*2 + tb) ^ rx) << 4);
            uint32_t bh[2], bl[2];
            LDSM2(bh, bhB + bofs);
            LDSM2(bl, blB + bofs);
            uint32_t aofs = (uint32_t)(((ks*2 + thi) ^ rx) << 4);
            #pragma unroll
            for (int i = 0; i < 4; i++) {
                uint32_t ah[4], al[4];
                uint32_t aa = a_rb + i*8192 + aofs;
                LDSM4(ah, aa);
                LDSM4(al, aa + 65536);
                MMA16816(c[i], ah, bh[0], bh[1]);
                MMA16816(c[i], al, bh[0], bh[1]);
                MMA16816(c[i], ah, bl[0], bl[1]);
            }
        }

        // fold into running row-max with per-column inv2 scaling
        const int col0 = mt*32 + wm*8 + (lane & 3)*2;
        const float iv0 = inv2_s[col0], iv1 = inv2_s[col0 + 1];
        #pragma unroll
        for (int i = 0; i < 4; i++) {
            mx[i][0] = fmaxf(mx[i][0], fmaxf(c[i][0]*iv0, c[i][1]*iv1));
            mx[i][1] = fmaxf(mx[i][1], fmaxf(c[i][2]*iv0, c[i][3]*iv1));
        }
        __syncthreads();     // all reads of stage mt&1 done before overwrite
    }

    // reduce across the 4 threads sharing each row (lane&3)
    #pragma unroll
    for (int i = 0; i < 4; i++)
        #pragma unroll
        for (int h = 0; h < 2; h++) {
            float v = mx[i][h];
            v = fmaxf(v, __shfl_xor_sync(0xffffffffu, v, 1));
            v = fmaxf(v, __shfl_xor_sync(0xffffffffu, v, 2));
            mx[i][h] = v;
        }

    if ((lane & 3) == 0) {
        int r = lane >> 2;
        #pragma unroll
        for (int i = 0; i < 4; i++) {
            red[wm*128 + wl*64 + i*16 + r]     = mx[i][0];
            red[wm*128 + wl*64 + i*16 + 8 + r] = mx[i][1];
        }
    }
    __syncthreads();

    if (tid < 128) {
        float m = red[tid];
        m = fmaxf(m, red[128 + tid]);
        m = fmaxf(m, red[256 + tid]);
        m = fmaxf(m, red[384 + tid]);
        out[((size_t)b*LL + l0 + tid)*PP + p] = m * inv1_s[tid];
    }
}

// ---------------------------------------------------------------------------
extern "C" void kernel_launch(void* const* d_in, const int* in_sizes, int n_in,
                              void* d_out, int out_size) {
    const float* s1  = (const float*)d_in[0];
    const float* s2  = (const float*)d_in[1];
    const float* ker = (const float*)d_in[2];
    float* out = (float*)d_out;

    cudaFuncSetAttribute(mpm_mma, cudaFuncAttributeMaxDynamicSharedMemorySize, SMEM_SZ);

    norms_kernel<<<BB*LL, 640>>>(s1, s2, ker);
    split_kernel<<<BB*LL*DD/8/256, 256>>>(s2);
    dim3 grid(2, PP, BB);
    mpm_mma<<<grid, 256, SMEM_SZ>>>(s1, ker, out);
}

// round 6
// speedup vs baseline: 5.8377x; 1.6790x over previous
#include <cuda_runtime.h>
#include <cuda_fp16.h>
#include <cstdint>

#define BB 16
#define LL 256
#define DD 256
#define PP 20

// Device-global scratch (no allocations allowed)
__device__ float g_inv1[BB*LL*PP];
__device__ float g_inv2[BB*LL*PP];
__device__ uint4 g_s2h[BB*LL*DD/8];   // fp16 s2, row-major (8 halfs per uint4)

// ---------------------------------------------------------------------------
// helpers
// ---------------------------------------------------------------------------
__device__ __forceinline__ uint32_t smem_u32(const void* p) {
    uint32_t a;
    asm("{ .reg .u64 t; cvta.to.shared.u64 t, %1; cvt.u32.u64 %0, t; }" : "=r"(a) : "l"(p));
    return a;
}
__device__ __forceinline__ uint32_t pk2h(float x, float y) {
    __half2 t = __floats2half2_rn(x, y);
    return reinterpret_cast<uint32_t&>(t);
}

#define LDSM4(r, addr) \
    asm volatile("ldmatrix.sync.aligned.m8n8.x4.shared.b16 {%0,%1,%2,%3}, [%4];" \
                 : "=r"((r)[0]), "=r"((r)[1]), "=r"((r)[2]), "=r"((r)[3]) : "r"(addr))
#define MMAF16(c, a, b0, b1) \
    asm volatile("mma.sync.aligned.m16n8k16.row.col.f32.f16.f16.f32 " \
                 "{%0,%1,%2,%3}, {%4,%5,%6,%7}, {%8,%9}, {%0,%1,%2,%3};" \
                 : "+f"((c)[0]), "+f"((c)[1]), "+f"((c)[2]), "+f"((c)[3]) \
                 : "r"((a)[0]), "r"((a)[1]), "r"((a)[2]), "r"((a)[3]), "r"(b0), "r"(b1))
#define CP16(dst, src) \
    asm volatile("cp.async.cg.shared.global [%0], [%1], 16;" :: "r"(dst), "l"(src))
#define CPCOMMIT() asm volatile("cp.async.commit_group;" ::: "memory")
#define CPWAIT0()  asm volatile("cp.async.wait_group 0;" ::: "memory")

// ---------------------------------------------------------------------------
// Kernel 1: inv-norms.  2 rows per block, warp per p.
// ---------------------------------------------------------------------------
__global__ void __launch_bounds__(640) norms_kernel(const float* __restrict__ s1,
                                                    const float* __restrict__ s2,
                                                    const float* __restrict__ ker) {
    __shared__ float sh1[2][DD], sh2[2][DD];
    int r0  = blockIdx.x * 2;
    int tid = threadIdx.x;
    if (tid < 512) {
        int row = tid >> 8, d = tid & 255;
        sh1[row][d] = s1[(size_t)(r0+row)*DD + d];
        sh2[row][d] = s2[(size_t)(r0+row)*DD + d];
    }
    __syncthreads();
    int p    = tid >> 5;
    int lane = tid & 31;
    const float* kp = ker + p*DD;
    float a10 = 0.f, a11 = 0.f, a20 = 0.f, a21 = 0.f;
    #pragma unroll
    for (int d = lane; d < DD; d += 32) {
        float k = kp[d];
        float w = k*k;
        a10 = fmaf(sh1[0][d]*sh1[0][d], w, a10);
        a11 = fmaf(sh1[1][d]*sh1[1][d], w, a11);
        a20 = fmaf(sh2[0][d]*sh2[0][d], w, a20);
        a21 = fmaf(sh2[1][d]*sh2[1][d], w, a21);
    }
    #pragma unroll
    for (int o = 16; o; o >>= 1) {
        a10 += __shfl_xor_sync(0xffffffffu, a10, o);
        a11 += __shfl_xor_sync(0xffffffffu, a11, o);
        a20 += __shfl_xor_sync(0xffffffffu, a20, o);
        a21 += __shfl_xor_sync(0xffffffffu, a21, o);
    }
    if (lane == 0) {
        g_inv1[(r0  )*PP + p] = rsqrtf(fmaxf(a10, 1e-12f));
        g_inv1[(r0+1)*PP + p] = rsqrtf(fmaxf(a11, 1e-12f));
        g_inv2[(r0  )*PP + p] = rsqrtf(fmaxf(a20, 1e-12f));
        g_inv2[(r0+1)*PP + p] = rsqrtf(fmaxf(a21, 1e-12f));
    }
}

// ---------------------------------------------------------------------------
// Kernel 1b: convert s2 -> fp16 in GMEM (single-precision B operand)
// ---------------------------------------------------------------------------
__global__ void __launch_bounds__(256) split_kernel(const float* __restrict__ s2) {
    int i = blockIdx.x*256 + threadIdx.x;        // uint4 index (8 floats)
    const float4* src = (const float4*)s2 + (size_t)i*2;
    float4 f0 = src[0], f1 = src[1];
    g_s2h[i] = make_uint4(pk2h(f0.x,f0.y), pk2h(f0.z,f0.w),
                          pk2h(f1.x,f1.y), pk2h(f1.z,f1.w));
}

// ---------------------------------------------------------------------------
// smem layout (bytes). Rows are 512B (256 fp16), XOR-swizzled 16B segments.
// ---------------------------------------------------------------------------
#define OFF_AHI  0                 // 128 rows x 512B = 65536
#define OFF_ALO  65536             // 65536
#define OFF_B    131072            // 2 stages x (64 rows x 512B = 32768)
#define OFF_W    196608            // 256 f32
#define OFF_INV1 197632            // 128 f32
#define OFF_INV2 198144            // 256 f32
#define SMEM_SZ  199168

__device__ __forceinline__ uint32_t swz(int row, int seg) {
    return (uint32_t)(row*512 + ((seg ^ (row & 7)) << 4));
}

// ---------------------------------------------------------------------------
// Kernel 2: per (b, p, l-half) 128x256x256 GEMM, fp16 2-term HMMA, fp32 acc.
// 8 warps; warp wid owns rows wid*16..wid*16+15 and all 64 n of each chunk.
// A = 64 * s1 * k^2 (hi+lo fp16); B = fp16(s2); epilogue folds inv2 (per
// column, before max) and inv1/64 (per row, after max).
// ---------------------------------------------------------------------------
__global__ void __launch_bounds__(256, 1) mpm_mma(const float* __restrict__ s1,
                                                  const float* __restrict__ ker,
                                                  float* __restrict__ out) {
    extern __shared__ char smem[];
    const uint32_t sbase = smem_u32(smem);
    float* w_s    = (float*)(smem + OFF_W);
    float* inv1_s = (float*)(smem + OFF_INV1);
    float* inv2_s = (float*)(smem + OFF_INV2);

    const int b   = blockIdx.z;
    const int p   = blockIdx.y;
    const int l0  = blockIdx.x * 128;
    const int tid = threadIdx.x;
    const int wid = tid >> 5;
    const int lane = tid & 31;

    const char* s2h_b = (const char*)g_s2h + (size_t)b*LL*DD*2;

    // ---- prefetch B chunk 0 (64 rows x 512B = 32KB) ----
    {
        const uint32_t dstb = sbase + OFF_B;
        #pragma unroll
        for (int j = 0; j < 8; j++) {
            int s = tid + j*256;                 // 16B segment 0..2047
            CP16(dstb + swz(s >> 5, s & 31), s2h_b + s*16);
        }
    }
    CPCOMMIT();

    // ---- per-p weights + inverse norms ----
    {
        float k = ker[p*DD + tid];               // tid spans 0..255 = D
        w_s[tid] = k*k;
        inv2_s[tid] = g_inv2[((size_t)b*LL + tid)*PP + p];
    }
    if (tid < 128)
        inv1_s[tid] = g_inv1[((size_t)b*LL + l0 + tid)*PP + p] * 0.015625f; // /64
    __syncthreads();

    // ---- build A once: a = 64 * s1 * k^2, fp16 hi + fp16 lo ----
    {
        const float4* s1b = (const float4*)(s1 + ((size_t)b*LL + l0)*DD);
        #pragma unroll 4
        for (int g = tid; g < 128*32; g += 256) {
            int row = g >> 5, grp = g & 31, d0 = grp * 8;
            float4 f0 = s1b[row*64 + grp*2];
            float4 f1 = s1b[row*64 + grp*2 + 1];
            float4 w0 = *(const float4*)(w_s + d0);
            float4 w1 = *(const float4*)(w_s + d0 + 4);
            float a[8] = { f0.x*w0.x*64.f, f0.y*w0.y*64.f, f0.z*w0.z*64.f, f0.w*w0.w*64.f,
                           f1.x*w1.x*64.f, f1.y*w1.y*64.f, f1.z*w1.z*64.f, f1.w*w1.w*64.f };
            float h[8], lo[8];
            #pragma unroll
            for (int i = 0; i < 8; i++) {
                h[i]  = __half2float(__float2half_rn(a[i]));
                lo[i] = a[i] - h[i];
            }
            uint32_t so = swz(row, grp);
            *(uint4*)(smem + OFF_AHI + so) =
                make_uint4(pk2h(h[0],h[1]), pk2h(h[2],h[3]), pk2h(h[4],h[5]), pk2h(h[6],h[7]));
            *(uint4*)(smem + OFF_ALO + so) =
                make_uint4(pk2h(lo[0],lo[1]),pk2h(lo[2],lo[3]),pk2h(lo[4],lo[5]),pk2h(lo[6],lo[7]));
        }
    }

    // ---- per-thread ldmatrix bases ----
    // A m16k16 x4: row = wid*16 + (lane&7) + ((lane>>3)&1)*8 ; k-seg half = lane>>4
    const int a_row = wid*16 + (lane & 7) + ((lane >> 3) & 1)*8;
    const uint32_t aB = sbase + OFF_AHI + (uint32_t)a_row*512;
    const int a_sx = (lane >> 4) ^ (a_row & 7);       // seg = (ks*2 + thi) ^ (row&7)
    // B n16k16 x4: row(n) = g*16 + (lane&7) + (lane>>4)*8 ; k half = (lane>>3)&1
    const int b_row = (lane & 7) + (lane >> 4)*8;     // + g*16
    const int b_kh  = (lane >> 3) & 1;

    float mx0 = __int_as_float(0xff800000), mx1 = mx0;

    for (int mt = 0; mt < 4; mt++) {
        CPWAIT0();
        __syncthreads();                    // chunk mt visible; prev stage free

        if (mt < 3) {                       // prefetch next into other stage
            const uint32_t dstb = sbase + OFF_B + ((mt+1)&1)*32768;
            const char* src = s2h_b + (size_t)(mt+1)*64*512;
            #pragma unroll
            for (int j = 0; j < 8; j++) {
                int s = tid + j*256;
                CP16(dstb + swz(s >> 5, s & 31), src + s*16);
            }
            CPCOMMIT();
        }

        const uint32_t bS = sbase + OFF_B + (mt&1)*32768;

        float c[8][4];
        #pragma unroll
        for (int i = 0; i < 8; i++)
            #pragma unroll
            for (int q = 0; q < 4; q++) c[i][q] = 0.f;

        #pragma unroll 4
        for (int ks = 0; ks < 16; ks++) {
            uint32_t ah[4], al[4];
            uint32_t aa = aB + (uint32_t)(((ks*2) ^ 0) + 0, ((ks*2 + (lane>>4)) ^ (a_row&7)) << 4);
            LDSM4(ah, aB + ((uint32_t)((ks*2 + (lane>>4)) ^ (a_row&7)) << 4));
            LDSM4(al, aB + 65536 + ((uint32_t)((ks*2 + (lane>>4)) ^ (a_row&7)) << 4));
            (void)aa;
            #pragma unroll
            for (int g = 0; g < 4; g++) {
                uint32_t bb[4];
                int brow = g*16 + b_row;
                LDSM4(bb, bS + (uint32_t)brow*512
                          + ((uint32_t)((ks*2 + b_kh) ^ (brow & 7)) << 4));
                MMAF16(c[g*2  ], ah, bb[0], bb[1]);
                MMAF16(c[g*2  ], al, bb[0], bb[1]);
                MMAF16(c[g*2+1], ah, bb[2], bb[3]);
                MMAF16(c[g*2+1], al, bb[2], bb[3]);
            }
        }

        // fold into running row-max with per-column inv2 scaling
        const int cb = mt*64 + (lane & 3)*2;
        #pragma unroll
        for (int t = 0; t < 8; t++) {
            float iv0 = inv2_s[cb + t*8];
            float iv1 = inv2_s[cb + t*8 + 1];
            mx0 = fmaxf(mx0, fmaxf(c[t][0]*iv0, c[t][1]*iv1));
            mx1 = fmaxf(mx1, fmaxf(c[t][2]*iv0, c[t][3]*iv1));
        }
    }

    // reduce across the 4 lanes sharing each row (lane&3)
    mx0 = fmaxf(mx0, __shfl_xor_sync(0xffffffffu, mx0, 1));
    mx0 = fmaxf(mx0, __shfl_xor_sync(0xffffffffu, mx0, 2));
    mx1 = fmaxf(mx1, __shfl_xor_sync(0xffffffffu, mx1, 1));
    mx1 = fmaxf(mx1, __shfl_xor_sync(0xffffffffu, mx1, 2));

    if ((lane & 3) == 0) {
        int r0 = wid*16 + (lane >> 2);       // rows r0 and r0+8
        out[((size_t)b*LL + l0 + r0    )*PP + p] = mx0 * inv1_s[r0];
        out[((size_t)b*LL + l0 + r0 + 8)*PP + p] = mx1 * inv1_s[r0 + 8];
    }
}

// ---------------------------------------------------------------------------
extern "C" void kernel_launch(void* const* d_in, const int* in_sizes, int n_in,
                              void* d_out, int out_size) {
    const float* s1  = (const float*)d_in[0];
    const float* s2  = (const float*)d_in[1];
    const float* ker = (const float*)d_in[2];
    float* out = (float*)d_out;

    cudaFuncSetAttribute(mpm_mma, cudaFuncAttributeMaxDynamicSharedMemorySize, SMEM_SZ);

    norms_kernel<<<BB*LL/2, 640>>>(s1, s2, ker);
    split_kernel<<<BB*LL*DD/8/256, 256>>>(s2);
    dim3 grid(2, PP, BB);
    mpm_mma<<<grid, 256, SMEM_SZ>>>(s1, ker, out);
}

// round 7
// speedup vs baseline: 6.6604x; 1.1409x over previous
#include <cuda_runtime.h>
#include <cuda_fp16.h>
#include <cstdint>

#define BB 16
#define LL 256
#define DD 256
#define PP 20

// Device-global scratch (no allocations allowed)
__device__ float g_inv1[BB*LL*PP];
__device__ float g_inv2[BB*LL*PP];
__device__ uint4 g_s2h[BB*LL*DD/8];   // fp16 s2, row-major (8 halfs per uint4)

// ---------------------------------------------------------------------------
// helpers
// ---------------------------------------------------------------------------
__device__ __forceinline__ uint32_t smem_u32(const void* p) {
    uint32_t a;
    asm("{ .reg .u64 t; cvta.to.shared.u64 t, %1; cvt.u32.u64 %0, t; }" : "=r"(a) : "l"(p));
    return a;
}
__device__ __forceinline__ uint32_t pk2h(float x, float y) {
    __half2 t = __floats2half2_rn(x, y);
    return reinterpret_cast<uint32_t&>(t);
}

#define LDSM4(r, addr) \
    asm volatile("ldmatrix.sync.aligned.m8n8.x4.shared.b16 {%0,%1,%2,%3}, [%4];" \
                 : "=r"((r)[0]), "=r"((r)[1]), "=r"((r)[2]), "=r"((r)[3]) : "r"(addr))
#define MMAF16(c, a, b0, b1) \
    asm volatile("mma.sync.aligned.m16n8k16.row.col.f32.f16.f16.f32 " \
                 "{%0,%1,%2,%3}, {%4,%5,%6,%7}, {%8,%9}, {%0,%1,%2,%3};" \
                 : "+f"((c)[0]), "+f"((c)[1]), "+f"((c)[2]), "+f"((c)[3]) \
                 : "r"((a)[0]), "r"((a)[1]), "r"((a)[2]), "r"((a)[3]), "r"(b0), "r"(b1))
#define CP16(dst, src) \
    asm volatile("cp.async.cg.shared.global [%0], [%1], 16;" :: "r"(dst), "l"(src))
#define CPCOMMIT() asm volatile("cp.async.commit_group;" ::: "memory")
#define CPWAIT0()  asm volatile("cp.async.wait_group 0;" ::: "memory")

// ---------------------------------------------------------------------------
// Kernel 1: inv-norms (4 rows/block, warp per p) + fused s2->fp16 split.
// ---------------------------------------------------------------------------
__global__ void __launch_bounds__(640) norms_kernel(const float* __restrict__ s1,
                                                    const float* __restrict__ s2,
                                                    const float* __restrict__ ker) {
    __shared__ float sh1[4][DD], sh2[4][DD];
    const int r0  = blockIdx.x * 4;
    const int tid = threadIdx.x;

    for (int i = tid; i < 4*DD; i += 640) {
        int row = i >> 8, d = i & 255;
        sh1[row][d] = s1[(size_t)(r0+row)*DD + d];
        sh2[row][d] = s2[(size_t)(r0+row)*DD + d];
    }
    __syncthreads();

    // fused split: write fp16 s2 rows (128 segments of 8 floats)
    if (tid < 128) {
        int row = tid >> 5, sg = tid & 31;
        const float* src = &sh2[row][sg*8];
        g_s2h[(size_t)(r0+row)*32 + sg] =
            make_uint4(pk2h(src[0],src[1]), pk2h(src[2],src[3]),
                       pk2h(src[4],src[5]), pk2h(src[6],src[7]));
    }

    const int p    = tid >> 5;
    const int lane = tid & 31;
    const float* kp = ker + p*DD;
    float n1[4] = {0.f,0.f,0.f,0.f}, n2[4] = {0.f,0.f,0.f,0.f};
    #pragma unroll
    for (int d = lane; d < DD; d += 32) {
        float k = kp[d];
        float w = k*k;
        #pragma unroll
        for (int r = 0; r < 4; r++) {
            n1[r] = fmaf(sh1[r][d]*sh1[r][d], w, n1[r]);
            n2[r] = fmaf(sh2[r][d]*sh2[r][d], w, n2[r]);
        }
    }
    #pragma unroll
    for (int o = 16; o; o >>= 1) {
        #pragma unroll
        for (int r = 0; r < 4; r++) {
            n1[r] += __shfl_xor_sync(0xffffffffu, n1[r], o);
            n2[r] += __shfl_xor_sync(0xffffffffu, n2[r], o);
        }
    }
    if (lane == 0) {
        #pragma unroll
        for (int r = 0; r < 4; r++) {
            g_inv1[(r0+r)*PP + p] = rsqrtf(fmaxf(n1[r], 1e-12f));
            g_inv2[(r0+r)*PP + p] = rsqrtf(fmaxf(n2[r], 1e-12f));
        }
    }
}

// ---------------------------------------------------------------------------
// smem layout (bytes). Rows are 512B (256 fp16), XOR-swizzled 16B segments.
// ---------------------------------------------------------------------------
#define OFF_A    0                 // 128 rows x 512B = 65536
#define OFF_B    65536             // 2 stages x (32 rows x 512B = 16384)
#define OFF_W    98304             // 256 f32
#define OFF_INV1 99328             // 128 f32
#define OFF_INV2 99840             // 256 f32
#define SMEM_SZ  100864

__device__ __forceinline__ uint32_t swz(int row, int seg) {
    return (uint32_t)(row*512 + ((seg ^ (row & 7)) << 4));
}

// ---------------------------------------------------------------------------
// Kernel 2: per (b, p, l-half) 128x256x256 GEMM, single fp16 HMMA, fp32 acc.
// 8 warps; warp wid owns rows wid*16..wid*16+15 and all 32 n of each chunk.
// A = 64 * s1 * k^2 (fp16); B = fp16(s2); epilogue folds inv2 (per column,
// before max) and inv1/64 (per row, after max).
// ---------------------------------------------------------------------------
__global__ void __launch_bounds__(256, 2) mpm_mma(const float* __restrict__ s1,
                                                  const float* __restrict__ ker,
                                                  float* __restrict__ out) {
    extern __shared__ char smem[];
    const uint32_t sbase = smem_u32(smem);
    float* w_s    = (float*)(smem + OFF_W);
    float* inv1_s = (float*)(smem + OFF_INV1);
    float* inv2_s = (float*)(smem + OFF_INV2);

    const int b   = blockIdx.z;
    const int p   = blockIdx.y;
    const int l0  = blockIdx.x * 128;
    const int tid = threadIdx.x;
    const int wid = tid >> 5;
    const int lane = tid & 31;

    const char* s2h_b = (const char*)g_s2h + (size_t)b*LL*DD*2;

    // ---- prefetch B chunk 0 (32 rows x 512B = 16KB) ----
    {
        const uint32_t dstb = sbase + OFF_B;
        #pragma unroll
        for (int j = 0; j < 4; j++) {
            int s = tid + j*256;                 // 16B segment 0..1023
            CP16(dstb + swz(s >> 5, s & 31), s2h_b + s*16);
        }
    }
    CPCOMMIT();

    // ---- per-p weights + inverse norms ----
    {
        float k = ker[p*DD + tid];               // tid spans 0..255 = D
        w_s[tid] = k*k;
        inv2_s[tid] = g_inv2[((size_t)b*LL + tid)*PP + p];
    }
    if (tid < 128)
        inv1_s[tid] = g_inv1[((size_t)b*LL + l0 + tid)*PP + p] * 0.015625f; // /64
    __syncthreads();

    // ---- build A once: a = fp16(64 * s1 * k^2) ----
    {
        const float4* s1b = (const float4*)(s1 + ((size_t)b*LL + l0)*DD);
        #pragma unroll 4
        for (int g = tid; g < 128*32; g += 256) {
            int row = g >> 5, grp = g & 31, d0 = grp * 8;
            float4 f0 = s1b[row*64 + grp*2];
            float4 f1 = s1b[row*64 + grp*2 + 1];
            float4 w0 = *(const float4*)(w_s + d0);
            float4 w1 = *(const float4*)(w_s + d0 + 4);
            *(uint4*)(smem + OFF_A + swz(row, grp)) =
                make_uint4(pk2h(f0.x*w0.x*64.f, f0.y*w0.y*64.f),
                           pk2h(f0.z*w0.z*64.f, f0.w*w0.w*64.f),
                           pk2h(f1.x*w1.x*64.f, f1.y*w1.y*64.f),
                           pk2h(f1.z*w1.z*64.f, f1.w*w1.w*64.f));
        }
    }

    // ---- per-thread ldmatrix bases ----
    // A m16k16 x4: row = wid*16 + (lane&7) + ((lane>>3)&1)*8 ; k-half = lane>>4
    const int a_row = wid*16 + (lane & 7) + ((lane >> 3) & 1)*8;
    const uint32_t aB = sbase + OFF_A + (uint32_t)a_row*512;
    const int a_kh = lane >> 4;
    const int a_rx = a_row & 7;
    // B n16k16 x4: row(n) = g*16 + (lane&7) + (lane>>4)*8 ; k-half = (lane>>3)&1
    const int b_row = (lane & 7) + (lane >> 4)*8;     // + g*16
    const int b_kh  = (lane >> 3) & 1;

    float mx0 = __int_as_float(0xff800000), mx1 = mx0;

    for (int mt = 0; mt < 8; mt++) {
        CPWAIT0();
        __syncthreads();                    // chunk mt visible; other stage free

        if (mt < 7) {                       // prefetch next into other stage
            const uint32_t dstb = sbase + OFF_B + ((mt+1)&1)*16384;
            const char* src = s2h_b + (size_t)(mt+1)*32*512;
            #pragma unroll
            for (int j = 0; j < 4; j++) {
                int s = tid + j*256;
                CP16(dstb + swz(s >> 5, s & 31), src + s*16);
            }
            CPCOMMIT();
        }

        const uint32_t bS = sbase + OFF_B + (mt&1)*16384;

        float c[4][4];
        #pragma unroll
        for (int i = 0; i < 4; i++)
            #pragma unroll
            for (int q = 0; q < 4; q++) c[i][q] = 0.f;

        #pragma unroll 8
        for (int ks = 0; ks < 16; ks++) {
            uint32_t ah[4];
            LDSM4(ah, aB + ((uint32_t)((ks*2 + a_kh) ^ a_rx) << 4));
            #pragma unroll
            for (int g = 0; g < 2; g++) {
                uint32_t bb[4];
                int brow = g*16 + b_row;
                LDSM4(bb, bS + (uint32_t)brow*512
                          + ((uint32_t)((ks*2 + b_kh) ^ (brow & 7)) << 4));
                MMAF16(c[g*2  ], ah, bb[0], bb[1]);
                MMAF16(c[g*2+1], ah, bb[2], bb[3]);
            }
        }

        // fold into running row-max with per-column inv2 scaling
        const int cb = mt*32 + (lane & 3)*2;
        #pragma unroll
        for (int t = 0; t < 4; t++) {
            float iv0 = inv2_s[cb + t*8];
            float iv1 = inv2_s[cb + t*8 + 1];
            mx0 = fmaxf(mx0, fmaxf(c[t][0]*iv0, c[t][1]*iv1));
            mx1 = fmaxf(mx1, fmaxf(c[t][2]*iv0, c[t][3]*iv1));
        }
    }

    // reduce across the 4 lanes sharing each row (lane&3)
    mx0 = fmaxf(mx0, __shfl_xor_sync(0xffffffffu, mx0, 1));
    mx0 = fmaxf(mx0, __shfl_xor_sync(0xffffffffu, mx0, 2));
    mx1 = fmaxf(mx1, __shfl_xor_sync(0xffffffffu, mx1, 1));
    mx1 = fmaxf(mx1, __shfl_xor_sync(0xffffffffu, mx1, 2));

    if ((lane & 3) == 0) {
        int r0 = wid*16 + (lane >> 2);       // rows r0 and r0+8
        out[((size_t)b*LL + l0 + r0    )*PP + p] = mx0 * inv1_s[r0];
        out[((size_t)b*LL + l0 + r0 + 8)*PP + p] = mx1 * inv1_s[r0 + 8];
    }
}

// ---------------------------------------------------------------------------
extern "C" void kernel_launch(void* const* d_in, const int* in_sizes, int n_in,
                              void* d_out, int out_size) {
    const float* s1  = (const float*)d_in[0];
    const float* s2  = (const float*)d_in[1];
    const float* ker = (const float*)d_in[2];
    float* out = (float*)d_out;

    cudaFuncSetAttribute(mpm_mma, cudaFuncAttributeMaxDynamicSharedMemorySize, SMEM_SZ);

    norms_kernel<<<BB*LL/4, 640>>>(s1, s2, ker);
    dim3 grid(2, PP, BB);
    mpm_mma<<<grid, 256, SMEM_SZ>>>(s1, ker, out);
}

// round 8
// speedup vs baseline: 7.6079x; 1.1423x over previous
#include <cuda_runtime.h>
#include <cuda_fp16.h>
#include <cstdint>

#define BB 16
#define LL 256
#define DD 256
#define PP 20

// Device-global scratch (no allocations allowed)
__device__ float g_inv1[BB*LL*PP];
__device__ float g_inv2[BB*LL*PP];
__device__ uint4 g_s2h[BB*LL*DD/8];   // fp16 s2, row-major (8 halfs per uint4)

// ---------------------------------------------------------------------------
// helpers
// ---------------------------------------------------------------------------
__device__ __forceinline__ uint32_t smem_u32(const void* p) {
    uint32_t a;
    asm("{ .reg .u64 t; cvta.to.shared.u64 t, %1; cvt.u32.u64 %0, t; }" : "=r"(a) : "l"(p));
    return a;
}
__device__ __forceinline__ uint32_t pk2h(float x, float y) {
    __half2 t = __floats2half2_rn(x, y);
    return reinterpret_cast<uint32_t&>(t);
}

#define LDSM4(r, addr) \
    asm volatile("ldmatrix.sync.aligned.m8n8.x4.shared.b16 {%0,%1,%2,%3}, [%4];" \
                 : "=r"((r)[0]), "=r"((r)[1]), "=r"((r)[2]), "=r"((r)[3]) : "r"(addr))
#define MMAF16(c, a0, a1, a2, a3, b0, b1) \
    asm volatile("mma.sync.aligned.m16n8k16.row.col.f32.f16.f16.f32 " \
                 "{%0,%1,%2,%3}, {%4,%5,%6,%7}, {%8,%9}, {%0,%1,%2,%3};" \
                 : "+f"((c)[0]), "+f"((c)[1]), "+f"((c)[2]), "+f"((c)[3]) \
                 : "r"(a0), "r"(a1), "r"(a2), "r"(a3), "r"(b0), "r"(b1))
#define CP16(dst, src) \
    asm volatile("cp.async.cg.shared.global [%0], [%1], 16;" :: "r"(dst), "l"(src))
#define CPCOMMIT() asm volatile("cp.async.commit_group;" ::: "memory")
#define CPWAIT0()  asm volatile("cp.async.wait_group 0;" ::: "memory")

// ---------------------------------------------------------------------------
// Kernel 1: inv-norms (8 rows/block, warp per p, lane owns 8 contiguous d)
// + fused s2 -> fp16 conversion.
// ---------------------------------------------------------------------------
__global__ void __launch_bounds__(640) norms_kernel(const float* __restrict__ s1,
                                                    const float* __restrict__ s2,
                                                    const float* __restrict__ ker) {
    __shared__ float sq1[8][DD], sq2[8][DD];   // squares, 16KB
    const int r0  = blockIdx.x * 8;
    const int tid = threadIdx.x;

    // load + square (+ fp16 split for s2). 512 threads x 8 floats.
    if (tid < 512) {
        int i   = tid & 255;          // 8 rows x 32 segs
        int row = i >> 5, sg = i & 31;
        if (tid < 256) {
            const float4* src = (const float4*)(s2 + (size_t)(r0+row)*DD + sg*8);
            float4 f0 = src[0], f1 = src[1];
            g_s2h[(size_t)(r0+row)*32 + sg] =
                make_uint4(pk2h(f0.x,f0.y), pk2h(f0.z,f0.w),
                           pk2h(f1.x,f1.y), pk2h(f1.z,f1.w));
            *(float4*)&sq2[row][sg*8]     = make_float4(f0.x*f0.x, f0.y*f0.y, f0.z*f0.z, f0.w*f0.w);
            *(float4*)&sq2[row][sg*8 + 4] = make_float4(f1.x*f1.x, f1.y*f1.y, f1.z*f1.z, f1.w*f1.w);
        } else {
            const float4* src = (const float4*)(s1 + (size_t)(r0+row)*DD + sg*8);
            float4 f0 = src[0], f1 = src[1];
            *(float4*)&sq1[row][sg*8]     = make_float4(f0.x*f0.x, f0.y*f0.y, f0.z*f0.z, f0.w*f0.w);
            *(float4*)&sq1[row][sg*8 + 4] = make_float4(f1.x*f1.x, f1.y*f1.y, f1.z*f1.z, f1.w*f1.w);
        }
    }
    __syncthreads();

    const int p    = tid >> 5;        // 0..19
    const int lane = tid & 31;
    const int d0   = lane * 8;

    float w[8];
    {
        float4 k0 = *(const float4*)(ker + p*DD + d0);
        float4 k1 = *(const float4*)(ker + p*DD + d0 + 4);
        w[0]=k0.x*k0.x; w[1]=k0.y*k0.y; w[2]=k0.z*k0.z; w[3]=k0.w*k0.w;
        w[4]=k1.x*k1.x; w[5]=k1.y*k1.y; w[6]=k1.z*k1.z; w[7]=k1.w*k1.w;
    }

    float a1[8], a2[8];
    #pragma unroll
    for (int r = 0; r < 8; r++) {
        float4 x0 = *(const float4*)&sq1[r][d0];
        float4 x1 = *(const float4*)&sq1[r][d0+4];
        float4 y0 = *(const float4*)&sq2[r][d0];
        float4 y1 = *(const float4*)&sq2[r][d0+4];
        float s1v = x0.x*w[0];  s1v = fmaf(x0.y,w[1],s1v); s1v = fmaf(x0.z,w[2],s1v); s1v = fmaf(x0.w,w[3],s1v);
        s1v = fmaf(x1.x,w[4],s1v); s1v = fmaf(x1.y,w[5],s1v); s1v = fmaf(x1.z,w[6],s1v); s1v = fmaf(x1.w,w[7],s1v);
        float s2v = y0.x*w[0];  s2v = fmaf(y0.y,w[1],s2v); s2v = fmaf(y0.z,w[2],s2v); s2v = fmaf(y0.w,w[3],s2v);
        s2v = fmaf(y1.x,w[4],s2v); s2v = fmaf(y1.y,w[5],s2v); s2v = fmaf(y1.z,w[6],s2v); s2v = fmaf(y1.w,w[7],s2v);
        a1[r] = s1v; a2[r] = s2v;
    }
    #pragma unroll
    for (int o = 16; o; o >>= 1)
        #pragma unroll
        for (int r = 0; r < 8; r++) {
            a1[r] += __shfl_xor_sync(0xffffffffu, a1[r], o);
            a2[r] += __shfl_xor_sync(0xffffffffu, a2[r], o);
        }
    #pragma unroll
    for (int r = 0; r < 8; r++)
        if (lane == r) {
            g_inv1[(r0+r)*PP + p] = rsqrtf(fmaxf(a1[r], 1e-12f));
            g_inv2[(r0+r)*PP + p] = rsqrtf(fmaxf(a2[r], 1e-12f));
        }
}

// ---------------------------------------------------------------------------
// smem layout (bytes)
// ---------------------------------------------------------------------------
#define OFF_A    0          // 128 rows x 512B (fp16, swizzled) = 65536
#define OFF_B    65536      // 2 slots x (64 rows x 256B) = 32768
#define OFF_W    98304      // 256 f32
#define OFF_INV1 99328      // 128 f32
#define OFF_INV2 99840      // 256 f32
#define OFF_RED  100864     // 2 x 128 f32
#define SMEM_SZ  101888

__device__ __forceinline__ uint32_t swzA(int row, int seg) {     // 512B rows, seg 0..31
    return (uint32_t)(row*512 + ((seg ^ (row & 7)) << 4));
}

// ---------------------------------------------------------------------------
// Kernel 2: per (b, p, l-half) 128x256x256 GEMM, fp16 HMMA, fp32 acc.
// Warp grid 4(m) x 2(n); warp tile m32 x n32. B streamed in k-half slices
// (64 n-rows x 128 k = 16KB), double-buffered. Fused row-max epilogue.
// ---------------------------------------------------------------------------
__global__ void __launch_bounds__(256, 2) mpm_mma(const float* __restrict__ s1,
                                                  const float* __restrict__ ker,
                                                  float* __restrict__ out) {
    extern __shared__ char smem[];
    const uint32_t sbase = smem_u32(smem);
    float* w_s    = (float*)(smem + OFF_W);
    float* inv1_s = (float*)(smem + OFF_INV1);
    float* inv2_s = (float*)(smem + OFF_INV2);
    float* red    = (float*)(smem + OFF_RED);

    const int b   = blockIdx.z;
    const int p   = blockIdx.y;
    const int l0  = blockIdx.x * 128;
    const int tid = threadIdx.x;
    const int wid = tid >> 5;
    const int lane = tid & 31;
    const int wm = wid & 3;            // m group (32 rows)
    const int wn = wid >> 2;           // n group (32 cols of 64-chunk)

    const char* s2h_b = (const char*)g_s2h + (size_t)b*LL*DD*2;

    // ---- prefetch half-chunk h into slot h&1 (64 rows x 256B, swizzled) ----
    auto prefetch = [&](int h) {
        const int chunk = h >> 1, kh = h & 1;
        const uint32_t dst = sbase + OFF_B + (h & 1)*16384;
        const char* src = s2h_b + (size_t)chunk*64*512 + kh*256;
        #pragma unroll
        for (int j = 0; j < 4; j++) {
            int s = tid + j*256;              // 0..1023: row*16 + seg
            int row = s >> 4, seg = s & 15;
            CP16(dst + row*256 + ((seg ^ (row & 7)) << 4), src + row*512 + seg*16);
        }
    };
    prefetch(0);
    CPCOMMIT();

    // ---- per-p weights + inverse norms ----
    {
        float k = ker[p*DD + tid];             // tid spans 0..255 = D
        w_s[tid] = k*k;
        inv2_s[tid] = g_inv2[((size_t)b*LL + tid)*PP + p];
    }
    if (tid < 128)
        inv1_s[tid] = g_inv1[((size_t)b*LL + l0 + tid)*PP + p] * 0.015625f; // /64
    __syncthreads();

    // ---- build A once: a = fp16(64 * s1 * k^2), 512B rows, swizzled ----
    {
        const float4* s1b = (const float4*)(s1 + ((size_t)b*LL + l0)*DD);
        #pragma unroll 4
        for (int g = tid; g < 128*32; g += 256) {
            int row = g >> 5, grp = g & 31, d0 = grp * 8;
            float4 f0 = s1b[row*64 + grp*2];
            float4 f1 = s1b[row*64 + grp*2 + 1];
            float4 w0 = *(const float4*)(w_s + d0);
            float4 w1 = *(const float4*)(w_s + d0 + 4);
            *(uint4*)(smem + OFF_A + swzA(row, grp)) =
                make_uint4(pk2h(f0.x*w0.x*64.f, f0.y*w0.y*64.f),
                           pk2h(f0.z*w0.z*64.f, f0.w*w0.w*64.f),
                           pk2h(f1.x*w1.x*64.f, f1.y*w1.y*64.f),
                           pk2h(f1.z*w1.z*64.f, f1.w*w1.w*64.f));
        }
    }

    // ---- per-thread ldmatrix bases ----
    const int rx   = lane & 7;
    // A m16k16 x4: row = base + (lane&7) + ((lane>>3)&1)*8 ; k-half = lane>>4
    const int a_row = wm*32 + rx + ((lane >> 3) & 1)*8;
    const uint32_t aA0 = sbase + OFF_A + (uint32_t)a_row*512;          // m-tile 0
    const uint32_t aA1 = aA0 + 16*512;                                  // m-tile 1 (+16 rows)
    const int a_kh = lane >> 4;
    // B n16k16 x4: row(n) = base + (lane&7) + (lane>>4)*8 ; k-half = (lane>>3)&1
    const int b_row0 = wn*32 + rx + (lane >> 4)*8;
    const int b_kh   = (lane >> 3) & 1;

    const float NEG_INF = __int_as_float(0xff800000);
    float mx[2][2] = {{NEG_INF, NEG_INF}, {NEG_INF, NEG_INF}};
    float c[2][4][4];

    for (int h = 0; h < 8; h++) {
        CPWAIT0();
        __syncthreads();               // slot h&1 filled; its previous readers done

        if (h < 7) { prefetch(h + 1); CPCOMMIT(); }

        const uint32_t bS = sbase + OFF_B + (h & 1)*16384;
        const int kbase = (h & 1)*8;

        if ((h & 1) == 0) {
            #pragma unroll
            for (int i = 0; i < 2; i++)
                #pragma unroll
                for (int t = 0; t < 4; t++)
                    #pragma unroll
                    for (int q = 0; q < 4; q++) c[i][t][q] = 0.f;
        }

        #pragma unroll
        for (int ks = 0; ks < 8; ks++) {
            uint32_t a0[4], a1[4];
            const uint32_t aseg = (uint32_t)((((kbase + ks)*2 + a_kh) ^ rx) << 4);
            LDSM4(a0, aA0 + aseg);
            LDSM4(a1, aA1 + aseg);
            const uint32_t bseg = (uint32_t)(((ks*2 + b_kh) ^ rx) << 4);
            #pragma unroll
            for (int g = 0; g < 2; g++) {
                uint32_t bb[4];
                LDSM4(bb, bS + (uint32_t)(b_row0 + g*16)*256 + bseg);
                MMAF16(c[0][g*2  ], a0[0],a0[1],a0[2],a0[3], bb[0], bb[1]);
                MMAF16(c[0][g*2+1], a0[0],a0[1],a0[2],a0[3], bb[2], bb[3]);
                MMAF16(c[1][g*2  ], a1[0],a1[1],a1[2],a1[3], bb[0], bb[1]);
                MMAF16(c[1][g*2+1], a1[0],a1[1],a1[2],a1[3], bb[2], bb[3]);
            }
        }

        if (h & 1) {   // chunk complete: fold row-max with per-column inv2
            const int cb = (h >> 1)*64 + wn*32 + (lane & 3)*2;
            #pragma unroll
            for (int t = 0; t < 4; t++) {
                float iv0 = inv2_s[cb + t*8];
                float iv1 = inv2_s[cb + t*8 + 1];
                #pragma unroll
                for (int i = 0; i < 2; i++) {
                    mx[i][0] = fmaxf(mx[i][0], fmaxf(c[i][t][0]*iv0, c[i][t][1]*iv1));
                    mx[i][1] = fmaxf(mx[i][1], fmaxf(c[i][t][2]*iv0, c[i][t][3]*iv1));
                }
            }
        }
    }

    // reduce across the 4 lanes sharing each row
    #pragma unroll
    for (int i = 0; i < 2; i++)
        #pragma unroll
        for (int r = 0; r < 2; r++) {
            float v = mx[i][r];
            v = fmaxf(v, __shfl_xor_sync(0xffffffffu, v, 1));
            v = fmaxf(v, __shfl_xor_sync(0xffffffffu, v, 2));
            mx[i][r] = v;
        }

    if ((lane & 3) == 0) {
        int r = lane >> 2;                      // 0..7
        float* rw = red + wn*128 + wm*32;
        rw[r]      = mx[0][0];
        rw[r + 8]  = mx[0][1];
        rw[r + 16] = mx[1][0];
        rw[r + 24] = mx[1][1];
    }
    __syncthreads();

    if (tid < 128) {
        float m = fmaxf(red[tid], red[128 + tid]) * inv1_s[tid];
        out[((size_t)b*LL + l0 + tid)*PP + p] = m;
    }
}

// ---------------------------------------------------------------------------
extern "C" void kernel_launch(void* const* d_in, const int* in_sizes, int n_in,
                              void* d_out, int out_size) {
    const float* s1  = (const float*)d_in[0];
    const float* s2  = (const float*)d_in[1];
    const float* ker = (const float*)d_in[2];
    float* out = (float*)d_out;

    cudaFuncSetAttribute(mpm_mma, cudaFuncAttributeMaxDynamicSharedMemorySize, SMEM_SZ);

    norms_kernel<<<BB*LL/8, 640>>>(s1, s2, ker);
    dim3 grid(2, PP, BB);
    mpm_mma<<<grid, 256, SMEM_SZ>>>(s1, ker, out);
}

// round 9
// speedup vs baseline: 7.7715x; 1.0215x over previous
#include <cuda_runtime.h>
#include <cuda_fp16.h>
#include <cstdint>

#define BB 16
#define LL 256
#define DD 256
#define PP 20

// Device-global scratch (no allocations allowed)
__device__ float g_inv1[BB*LL*PP];
__device__ float g_inv2[BB*LL*PP];
__device__ uint4 g_s2h[BB*LL*DD/8];   // fp16 s2, row-major (8 halfs per uint4)

// ---------------------------------------------------------------------------
// helpers
// ---------------------------------------------------------------------------
__device__ __forceinline__ uint32_t smem_u32(const void* p) {
    uint32_t a;
    asm("{ .reg .u64 t; cvta.to.shared.u64 t, %1; cvt.u32.u64 %0, t; }" : "=r"(a) : "l"(p));
    return a;
}
__device__ __forceinline__ uint32_t pk2h(float x, float y) {
    __half2 t = __floats2half2_rn(x, y);
    return reinterpret_cast<uint32_t&>(t);
}

#define LDSM4(r, addr) \
    asm volatile("ldmatrix.sync.aligned.m8n8.x4.shared.b16 {%0,%1,%2,%3}, [%4];" \
                 : "=r"((r)[0]), "=r"((r)[1]), "=r"((r)[2]), "=r"((r)[3]) : "r"(addr))
#define MMAF16(c, a0, a1, a2, a3, b0, b1) \
    asm volatile("mma.sync.aligned.m16n8k16.row.col.f32.f16.f16.f32 " \
                 "{%0,%1,%2,%3}, {%4,%5,%6,%7}, {%8,%9}, {%0,%1,%2,%3};" \
                 : "+f"((c)[0]), "+f"((c)[1]), "+f"((c)[2]), "+f"((c)[3]) \
                 : "r"(a0), "r"(a1), "r"(a2), "r"(a3), "r"(b0), "r"(b1))
#define CP16(dst, src) \
    asm volatile("cp.async.cg.shared.global [%0], [%1], 16;" :: "r"(dst), "l"(src))
#define CPCOMMIT() asm volatile("cp.async.commit_group;" ::: "memory")
#define CPWAIT0()  asm volatile("cp.async.wait_group 0;" ::: "memory")

// ---------------------------------------------------------------------------
// Kernel 1: inv-norms, shuffle-free. 12 rows/block over unified row space
// r in [0,8192): r<4096 -> s1 row r, else s2 row r-4096.
// Phase 1: load rows, square into smem (+ fp16 convert for s2 rows).
// Phase 2: thread (row,p) does a 256-FMA dot from smem, direct store.
// ---------------------------------------------------------------------------
#define NR 12
#define WPAD 260
__global__ void __launch_bounds__(256) norms_kernel(const float* __restrict__ s1,
                                                    const float* __restrict__ s2,
                                                    const float* __restrict__ ker) {
    __shared__ float sq[NR][DD];        // 12 KB
    __shared__ float wp[PP*WPAD];       // ~20.3 KB, padded rows

    const int r0  = blockIdx.x * NR;
    const int tid = threadIdx.x;

    // w = k^2 into padded smem (1280 float4 / 256 threads = 5 each)
    #pragma unroll
    for (int j = 0; j < 5; j++) {
        int i = tid + j*256;                 // 0..1279
        int p = i >> 6, d0 = (i & 63) * 4;
        float4 k = ((const float4*)ker)[i];
        *(float4*)&wp[p*WPAD + d0] = make_float4(k.x*k.x, k.y*k.y, k.z*k.z, k.w*k.w);
    }

    // rows: 12 rows x 32 8-float segments = 384 items
    for (int i = tid; i < NR*32; i += 256) {
        int row = i >> 5, sg = i & 31;
        int gr = r0 + row;
        int cr = gr < 8192 ? gr : 0;
        const float4* src = (cr < 4096)
            ? (const float4*)(s1 + (size_t)cr*DD + sg*8)
            : (const float4*)(s2 + (size_t)(cr-4096)*DD + sg*8);
        float4 f0 = src[0], f1 = src[1];
        *(float4*)&sq[row][sg*8]     = make_float4(f0.x*f0.x, f0.y*f0.y, f0.z*f0.z, f0.w*f0.w);
        *(float4*)&sq[row][sg*8 + 4] = make_float4(f1.x*f1.x, f1.y*f1.y, f1.z*f1.z, f1.w*f1.w);
        if (gr < 8192 && gr >= 4096)         // fused fp16 convert of s2
            g_s2h[(size_t)(gr-4096)*32 + sg] =
                make_uint4(pk2h(f0.x,f0.y), pk2h(f0.z,f0.w),
                           pk2h(f1.x,f1.y), pk2h(f1.z,f1.w));
    }
    __syncthreads();

    if (tid < NR*PP) {
        int row = tid / PP, p = tid % PP;
        int gr = r0 + row;
        if (gr < 8192) {
            const float* sr = sq[row];
            const float* wr = wp + p*WPAD;
            float acc = 0.f;
            #pragma unroll 8
            for (int d0 = 0; d0 < DD; d0 += 4) {
                float4 sv = *(const float4*)(sr + d0);
                float4 wv = *(const float4*)(wr + d0);
                acc = fmaf(sv.x, wv.x, acc);
                acc = fmaf(sv.y, wv.y, acc);
                acc = fmaf(sv.z, wv.z, acc);
                acc = fmaf(sv.w, wv.w, acc);
            }
            float inv = rsqrtf(fmaxf(acc, 1e-12f));
            if (gr < 4096) g_inv1[gr*PP + p] = inv;
            else           g_inv2[(gr-4096)*PP + p] = inv;
        }
    }
}

// ---------------------------------------------------------------------------
// smem layout (bytes)
// ---------------------------------------------------------------------------
#define OFF_A    0          // 128 rows x 512B (fp16, swizzled) = 65536
#define OFF_B    65536      // 2 slots x (64 rows x 512B = 32768)
#define OFF_W    131072     // 256 f32
#define OFF_INV1 132096     // 128 f32
#define OFF_INV2 132608     // 256 f32
#define OFF_RED  133632     // 2 x 128 f32
#define SMEM_SZ  134656

__device__ __forceinline__ uint32_t swzA(int row, int seg) {     // 512B rows, seg 0..31
    return (uint32_t)(row*512 + ((seg ^ (row & 7)) << 4));
}

// ---------------------------------------------------------------------------
// Kernel 2: per (b, p, l-half) 128x256x256 GEMM, fp16 HMMA, fp32 acc.
// A fragments (m32 x k256 per warp) persistent in registers; mainloop reads
// only B from smem. B streamed as full-k n64 chunks (32KB), double-buffered.
// Warp grid 4(m) x 2(n); warp tile m32 x n32. Fused row-max epilogue.
// ---------------------------------------------------------------------------
__global__ void __launch_bounds__(256, 1) mpm_mma(const float* __restrict__ s1,
                                                  const float* __restrict__ ker,
                                                  float* __restrict__ out) {
    extern __shared__ char smem[];
    const uint32_t sbase = smem_u32(smem);
    float* w_s    = (float*)(smem + OFF_W);
    float* inv1_s = (float*)(smem + OFF_INV1);
    float* inv2_s = (float*)(smem + OFF_INV2);
    float* red    = (float*)(smem + OFF_RED);

    const int b   = blockIdx.z;
    const int p   = blockIdx.y;
    const int l0  = blockIdx.x * 128;
    const int tid = threadIdx.x;
    const int wid = tid >> 5;
    const int lane = tid & 31;
    const int wm = wid & 3;            // m group (32 rows)
    const int wn = wid >> 2;           // n group (32 of 64-chunk)

    const char* s2h_b = (const char*)g_s2h + (size_t)b*LL*DD*2;

    // ---- prefetch B chunk c (64 n-rows x 256 k fp16 = 32KB, swizzled) ----
    auto prefetch = [&](int c) {
        const uint32_t dst = sbase + OFF_B + (c & 1)*32768;
        const char* src = s2h_b + (size_t)c*64*512;
        #pragma unroll
        for (int j = 0; j < 8; j++) {
            int s = tid + j*256;              // 0..2047: row*32 + seg
            int row = s >> 5, seg = s & 31;
            CP16(dst + swzA(row, seg), src + row*512 + seg*16);
        }
    };
    prefetch(0);
    CPCOMMIT();

    // ---- per-p weights + inverse norms ----
    {
        float k = ker[p*DD + tid];             // tid spans 0..255 = D
        w_s[tid] = k*k;
        inv2_s[tid] = g_inv2[((size_t)b*LL + tid)*PP + p];
    }
    if (tid < 128)
        inv1_s[tid] = g_inv1[((size_t)b*LL + l0 + tid)*PP + p] * 0.015625f; // /64
    __syncthreads();

    // ---- build A: a = fp16(64 * s1 * k^2), 512B rows, swizzled ----
    {
        const float4* s1b = (const float4*)(s1 + ((size_t)b*LL + l0)*DD);
        #pragma unroll 4
        for (int g = tid; g < 128*32; g += 256) {
            int row = g >> 5, grp = g & 31, d0 = grp * 8;
            float4 f0 = s1b[row*64 + grp*2];
            float4 f1 = s1b[row*64 + grp*2 + 1];
            float4 w0 = *(const float4*)(w_s + d0);
            float4 w1 = *(const float4*)(w_s + d0 + 4);
            *(uint4*)(smem + OFF_A + swzA(row, grp)) =
                make_uint4(pk2h(f0.x*w0.x*64.f, f0.y*w0.y*64.f),
                           pk2h(f0.z*w0.z*64.f, f0.w*w0.w*64.f),
                           pk2h(f1.x*w1.x*64.f, f1.y*w1.y*64.f),
                           pk2h(f1.z*w1.z*64.f, f1.w*w1.w*64.f));
        }
    }
    __syncthreads();

    // ---- load A fragments: m32 x k256 per warp = 128 regs, once ----
    const int rx = lane & 7;
    const int a_row = wm*32 + rx + ((lane >> 3) & 1)*8;
    const uint32_t aA = sbase + OFF_A + (uint32_t)a_row*512;
    const int a_kh = lane >> 4;

    uint32_t af[2][16][4];
    #pragma unroll
    for (int t = 0; t < 2; t++)
        #pragma unroll
        for (int ks = 0; ks < 16; ks++)
            LDSM4(af[t][ks], aA + (uint32_t)t*(16*512)
                           + ((uint32_t)((ks*2 + a_kh) ^ rx) << 4));

    // B n16k16 x4: row(n) = base + (lane&7) + (lane>>4)*8 ; k-half = (lane>>3)&1
    const int b_row0 = wn*32 + rx + (lane >> 4)*8;
    const int b_kh   = (lane >> 3) & 1;

    const float NEG_INF = __int_as_float(0xff800000);
    float mx[2][2] = {{NEG_INF, NEG_INF}, {NEG_INF, NEG_INF}};

    for (int mt = 0; mt < 4; mt++) {
        CPWAIT0();
        __syncthreads();               // chunk mt resident; prior readers done

        if (mt < 3) { prefetch(mt + 1); CPCOMMIT(); }

        const uint32_t bS = sbase + OFF_B + (mt & 1)*32768;

        float c[2][4][4];
        #pragma unroll
        for (int i = 0; i < 2; i++)
            #pragma unroll
            for (int t = 0; t < 4; t++)
                #pragma unroll
                for (int q = 0; q < 4; q++) c[i][t][q] = 0.f;

        #pragma unroll
        for (int ks = 0; ks < 16; ks++) {
            const uint32_t bseg = (uint32_t)(((ks*2 + b_kh) ^ rx) << 4);
            #pragma unroll
            for (int g = 0; g < 2; g++) {
                uint32_t bb[4];
                LDSM4(bb, bS + (uint32_t)(b_row0 + g*16)*512 + bseg);
                MMAF16(c[0][g*2  ], af[0][ks][0],af[0][ks][1],af[0][ks][2],af[0][ks][3], bb[0], bb[1]);
                MMAF16(c[0][g*2+1], af[0][ks][0],af[0][ks][1],af[0][ks][2],af[0][ks][3], bb[2], bb[3]);
                MMAF16(c[1][g*2  ], af[1][ks][0],af[1][ks][1],af[1][ks][2],af[1][ks][3], bb[0], bb[1]);
                MMAF16(c[1][g*2+1], af[1][ks][0],af[1][ks][1],af[1][ks][2],af[1][ks][3], bb[2], bb[3]);
            }
        }

        // fold row-max with per-column inv2
        const int cb = mt*64 + wn*32 + (lane & 3)*2;
        #pragma unroll
        for (int t = 0; t < 4; t++) {
            float iv0 = inv2_s[cb + t*8];
            float iv1 = inv2_s[cb + t*8 + 1];
            #pragma unroll
            for (int i = 0; i < 2; i++) {
                mx[i][0] = fmaxf(mx[i][0], fmaxf(c[i][t][0]*iv0, c[i][t][1]*iv1));
                mx[i][1] = fmaxf(mx[i][1], fmaxf(c[i][t][2]*iv0, c[i][t][3]*iv1));
            }
        }
    }

    // reduce across the 4 lanes sharing each row
    #pragma unroll
    for (int i = 0; i < 2; i++)
        #pragma unroll
        for (int r = 0; r < 2; r++) {
            float v = mx[i][r];
            v = fmaxf(v, __shfl_xor_sync(0xffffffffu, v, 1));
            v = fmaxf(v, __shfl_xor_sync(0xffffffffu, v, 2));
            mx[i][r] = v;
        }

    if ((lane & 3) == 0) {
        int r = lane >> 2;                      // 0..7
        float* rw = red + wn*128 + wm*32;
        rw[r]      = mx[0][0];
        rw[r + 8]  = mx[0][1];
        rw[r + 16] = mx[1][0];
        rw[r + 24] = mx[1][1];
    }
    __syncthreads();

    if (tid < 128) {
        float m = fmaxf(red[tid], red[128 + tid]) * inv1_s[tid];
        out[((size_t)b*LL + l0 + tid)*PP + p] = m;
    }
}

// ---------------------------------------------------------------------------
extern "C" void kernel_launch(void* const* d_in, const int* in_sizes, int n_in,
                              void* d_out, int out_size) {
    const float* s1  = (const float*)d_in[0];
    const float* s2  = (const float*)d_in[1];
    const float* ker = (const float*)d_in[2];
    float* out = (float*)d_out;

    cudaFuncSetAttribute(mpm_mma, cudaFuncAttributeMaxDynamicSharedMemorySize, SMEM_SZ);

    norms_kernel<<<(8192 + NR - 1)/NR, 256>>>(s1, s2, ker);
    dim3 grid(2, PP, BB);
    mpm_mma<<<grid, 256, SMEM_SZ>>>(s1, ker, out);
}